// round 12
// baseline (speedup 1.0000x reference)
#include <cuda_runtime.h>
#include <stdint.h>

#define NBATCH 16
#define TT     2048
#define SS     2048
#define HH     64

typedef unsigned long long ull;

__device__ __forceinline__ ull umax64(ull a, ull b) { return a > b ? a : b; }
__device__ __forceinline__ ull umin64(ull a, ull b) { return a < b ? a : b; }

// key = (sortable_score << 8) | (127 - expanded_idx); numeric DESC order ==
// desc by score, ties by ascending index (replicates lax.top_k exactly,
// given equal pos -> bit-equal score).
__device__ __forceinline__ ull enc_key(float s, int idx) {
    unsigned u  = __float_as_uint(s);
    unsigned su = (u & 0x80000000u) ? ~u : (u | 0x80000000u);
    return ((ull)su << 8) | (ull)(127 - idx);
}
__device__ __forceinline__ float dec_score(ull k) {
    unsigned su = (unsigned)(k >> 8);
    unsigned u  = (su & 0x80000000u) ? (su & 0x7FFFFFFFu) : ~su;
    return __uint_as_float(u);
}

__global__ __launch_bounds__(128, 16)
void tree_attn_kernel(const float* __restrict__ q,
                      const float* __restrict__ kmat,
                      const float* __restrict__ v,
                      float* __restrict__ out)
{
    // per-warp private scratch (one row per warp; NO block barriers anywhere)
    __shared__ float              sc_s[4][66];   // scores by child slot (+pad)
    __shared__ int                zpar_s[4][64]; // parent z values
    __shared__ __align__(8) int2  fl_s[4][66];   // compacted fresh list (+pad)
    __shared__ __align__(16) ull  pk_s[4][64];   // epilogue (pos,p) packs

    const int wid  = threadIdx.x >> 5;
    const int lane = threadIdx.x & 31;
    const int row  = blockIdx.x * 4 + wid;
    const int n    = row >> 11;
    const int t    = row & (TT - 1);
    const float tsrc = (float)(t + 1);
    const int l16  = lane & 15;
    const int hw   = lane >> 4;          // half-warp 0/1
    const unsigned FULL = 0xffffffffu;
    const unsigned LT   = (1u << lane) - 1u;

    float* scw   = sc_s[wid];
    int*   zparw = zpar_s[wid];
    int2*  flw   = fl_s[wid];
    ull*   pkw   = pk_s[wid];

    const float* kbase = kmat + (size_t)n * SS * HH;
    const float4 q4 = ((const float4*)(q + ((size_t)(n * TT + t)) * HH))[l16];

    // R3-verbatim pinned scoring tree (bit-matches the reference einsum;
    // the reduction order must NOT change). 2 candidates per warp pass.
    #define SCORE2(PP, SLOT)                                                  \
        {                                                                     \
            const float4* krow = (const float4*)(kbase + (size_t)(PP) * HH);  \
            float4 k4 = krow[l16];                                            \
            float part = q4.x * k4.x + q4.y * k4.y + q4.z * k4.z + q4.w * k4.w;\
            part += __shfl_xor_sync(FULL, part, 1);                           \
            part += __shfl_xor_sync(FULL, part, 2);                           \
            part += __shfl_xor_sync(FULL, part, 4);                           \
            part += __shfl_xor_sync(FULL, part, 8);                           \
            if (l16 == 0) scw[SLOT] = part;                                   \
        }

    // ------------- it0: 32 fresh candidates (z = c), w2 = 32 ----------------
    ull key;
    {
        const float r = tsrc * (1.0f / 32.0f);
        #pragma unroll
        for (int j = 0; j < 16; ++j) {
            int c  = 2 * j + hw;
            int pp = min((int)rintf((float)c * r), SS - 1);
            SCORE2(pp, c)
        }
        __syncwarp();
        key = enc_key(scw[lane], lane);      // idx == z at level 0
        #pragma unroll
        for (int kk = 2; kk <= 32; kk <<= 1)
            #pragma unroll
            for (int j2 = kk >> 1; j2 > 0; j2 >>= 1) {
                ull p = __shfl_xor_sync(FULL, key, j2);
                bool mx = (((lane & j2) == 0) == ((lane & kk) == 0));
                key = mx ? umax64(key, p) : umin64(key, p);
            }
    }

    // 2-packed state: E0/E1 = kept keys at slots 2t/2t+1; zp0/zp1 parent z.
    // it0 kept 32 -> pad slots 32..63 with key 0 (below any real key).
    ull E0, E1; int zp0, zp1;
    {
        ull k0 = __shfl_sync(FULL, key, (2 * lane) & 31);
        ull k1 = __shfl_sync(FULL, key, (2 * lane + 1) & 31);
        bool lo = lane < 16;
        E0 = lo ? k0 : 0ull;
        E1 = lo ? k1 : 0ull;
        zp0 = lo ? (127 - (int)(k0 & 0xFF)) : 0;
        zp1 = lo ? (127 - (int)(k1 & 0xFF)) : 0;
    }

    // ------------- levels it = 1..6 (it1: 32 parents, else 64) --------------
    #pragma unroll 1
    for (int it = 1; it < 7; ++it) {
        const int   nPar = (it == 1) ? 32 : 64;
        const float r    = tsrc / (float)(32 << it);
        const int   a0   = 2 * lane, a1 = 2 * lane + 1;   // parent ranks

        // per-candidate collision skip: odd child landing on the even
        // sibling's token has a score bit-equal to the parent's -> inherit.
        int pE0 = min((int)rintf((float)(2 * zp0) * r),     SS - 1);
        int pO0 = min((int)rintf((float)(2 * zp0 + 1) * r), SS - 1);
        int pE1 = min((int)rintf((float)(2 * zp1) * r),     SS - 1);
        int pO1 = min((int)rintf((float)(2 * zp1 + 1) * r), SS - 1);
        bool real0 = a0 < nPar;
        bool real1 = a1 < nPar;
        bool fresh0 = real0 && (pO0 != pE0);
        bool fresh1 = real1 && (pO1 != pE1);

        if (real0 && (!fresh0 || !fresh1)) {
            // write inherited scores (pair store when both inherit)
            if (!fresh0 && !fresh1 && real1) {
                *(float2*)(scw + a0) = make_float2(dec_score(E0), dec_score(E1));
            } else {
                if (!fresh0)          scw[a0] = dec_score(E0);
                if (real1 && !fresh1) scw[a1] = dec_score(E1);
            }
        }
        *(int2*)(zparw + a0) = make_int2(zp0, zp1);

        // compact fresh candidates into a dense worklist (pos, slot)
        unsigned m0 = __ballot_sync(FULL, fresh0);
        unsigned m1 = __ballot_sync(FULL, fresh1);
        int c0 = __popc(m0);
        int nF = c0 + __popc(m1);
        if (fresh0) flw[__popc(m0 & LT)]      = make_int2(pO0, a0);
        if (fresh1) flw[c0 + __popc(m1 & LT)] = make_int2(pO1, a1);
        if (lane == 0) flw[nF] = make_int2(0, 64);   // pad entry -> scw[64]
        __syncwarp();

        // uniform scoring passes over the compacted list (2 per pass)
        for (int j = 0; j < nF; j += 2) {
            int2 ent = flw[j + hw];
            SCORE2(ent.x, ent.y)
        }
        __syncwarp();

        // odd keys 2/lane (expanded idx = 2*rank+1); pads -> 0
        float2 sc2 = *(const float2*)(scw + a0);     // one LDS.64
        ull O0 = real0 ? enc_key(sc2.x, 2 * a0 + 1) : 0ull;
        ull O1 = real1 ? enc_key(sc2.y, 2 * a1 + 1) : 0ull;

        // desc bitonic sort of 64 odds, 2/lane (R8/R9-validated network)
        #pragma unroll
        for (int kk = 2; kk <= 64; kk <<= 1) {
            #pragma unroll
            for (int j2 = kk >> 1; j2 > 0; j2 >>= 1) {
                bool grp0 = ((a0 & kk) == 0);
                if (j2 == 1) {
                    ull mxv = umax64(O0, O1), mnv = umin64(O0, O1);
                    O0 = grp0 ? mxv : mnv;
                    O1 = grp0 ? mnv : mxv;
                } else {
                    int jh = j2 >> 1;
                    ull b0 = __shfl_xor_sync(FULL, O0, jh);
                    ull b1 = __shfl_xor_sync(FULL, O1, jh);
                    bool mx = (((lane & jh) == 0) == grp0);
                    O0 = mx ? umax64(O0, b0) : umin64(O0, b0);
                    O1 = mx ? umax64(O1, b1) : umin64(O1, b1);
                }
            }
        }

        // combine: evens (sorted, reindexed to idx 2*slot) vs reversed odds
        ull rev0 = __shfl_sync(FULL, O1, 31 - lane);
        ull rev1 = __shfl_sync(FULL, O0, 31 - lane);
        E0 = (E0 & ~0xFFull) | (ull)(127 - 4 * lane);
        E1 = (E1 & ~0xFFull) | (ull)(127 - (4 * lane + 2));
        E0 = umax64(E0, rev0);              // top-64 multiset, bitonic
        E1 = umax64(E1, rev1);

        // 6-stage desc merge -> sorted (skipped at final level: epilogue is
        // set-order invariant — validated R6/R8/R9)
        if (it < 6) {
            #pragma unroll
            for (int j2 = 32; j2 > 1; j2 >>= 1) {
                int jh = j2 >> 1;
                ull b0 = __shfl_xor_sync(FULL, E0, jh);
                ull b1 = __shfl_xor_sync(FULL, E1, jh);
                bool mx = ((lane & jh) == 0);
                E0 = mx ? umax64(E0, b0) : umin64(E0, b0);
                E1 = mx ? umax64(E1, b1) : umin64(E1, b1);
            }
            ull mxv = umax64(E0, E1), mnv = umin64(E0, E1);
            E0 = mxv; E1 = mnv;
        }

        // decode next-level parents (zparw stable during this level)
        int e0 = 127 - (int)(E0 & 0xFF);
        int e1 = 127 - (int)(E1 & 0xFF);
        zp0 = 2 * zparw[e0 >> 1] + (e0 & 1);
        zp1 = 2 * zparw[e1 >> 1] + (e1 & 1);
    }

    // ------------- final attention over the 64 kept (warp-local) ------------
    {
        const float rf = tsrc * (1.0f / 2048.0f);
        int pos0 = min((int)rintf((float)zp0 * rf), SS - 1);
        int pos1 = min((int)rintf((float)zp1 * rf), SS - 1);
        bool v0 = ((float)pos0 < tsrc);
        bool v1 = ((float)pos1 < tsrc);
        float a0 = v0 ? dec_score(E0) * 0.125f : -1e9f;   // 1/sqrt(64)
        float a1 = v1 ? dec_score(E1) * 0.125f : -1e9f;

        float m = fmaxf(a0, a1);
        m = fmaxf(m, __shfl_xor_sync(FULL, m, 16));
        m = fmaxf(m, __shfl_xor_sync(FULL, m, 8));
        m = fmaxf(m, __shfl_xor_sync(FULL, m, 4));
        m = fmaxf(m, __shfl_xor_sync(FULL, m, 2));
        m = fmaxf(m, __shfl_xor_sync(FULL, m, 1));

        float e0 = v0 ? expf(a0 - m) : 0.0f;   // invalid: ref underflows to 0
        float e1 = v1 ? expf(a1 - m) : 0.0f;
        float s = e0 + e1;
        s += __shfl_xor_sync(FULL, s, 16);
        s += __shfl_xor_sync(FULL, s, 8);
        s += __shfl_xor_sync(FULL, s, 4);
        s += __shfl_xor_sync(FULL, s, 2);
        s += __shfl_xor_sync(FULL, s, 1);

        float p0 = (s > 0.0f) ? (e0 / s) : 0.0f;  // all-invalid -> 0 (ref)
        float p1 = (s > 0.0f) ? (e1 / s) : 0.0f;

        // pack (pos, p) per slot; one STS.128 per lane
        ull pk0 = ((ull)(unsigned)pos0 << 32) | __float_as_uint(p0);
        ull pk1 = ((ull)(unsigned)pos1 << 32) | __float_as_uint(p1);
        ((ulonglong2*)pkw)[lane] = make_ulonglong2(pk0, pk1);
        __syncwarp();

        // split gather: lanes 0-15 accumulate even entries, 16-31 odd entries;
        // each lane owns 4 h-values (float4 loads -> LDG.128, half the LDGs).
        const int hb = 4 * l16;
        const float* vb = v + (size_t)n * SS * HH + hb;
        float4 acc = make_float4(0.f, 0.f, 0.f, 0.f);
        #pragma unroll 8
        for (int kk = hw; kk < 64; kk += 2) {
            ull pv = pkw[kk];                 // LDS.64 broadcast per half
            int   pos = (int)(pv >> 32);
            float p   = __uint_as_float((unsigned)pv);
            float4 v4 = *(const float4*)(vb + (size_t)pos * HH);
            acc.x = fmaf(p, v4.x, acc.x);
            acc.y = fmaf(p, v4.y, acc.y);
            acc.z = fmaf(p, v4.z, acc.z);
            acc.w = fmaf(p, v4.w, acc.w);
        }
        // cross-half combine (even-partial + odd-partial)
        acc.x += __shfl_xor_sync(FULL, acc.x, 16);
        acc.y += __shfl_xor_sync(FULL, acc.y, 16);
        acc.z += __shfl_xor_sync(FULL, acc.z, 16);
        acc.w += __shfl_xor_sync(FULL, acc.w, 16);
        if (lane < 16)
            ((float4*)(out + ((size_t)(n * TT + t)) * HH))[l16] = acc;
    }
    #undef SCORE2
}

extern "C" void kernel_launch(void* const* d_in, const int* in_sizes, int n_in,
                              void* d_out, int out_size)
{
    const float* q = (const float*)d_in[0];
    const float* k = (const float*)d_in[1];
    const float* v = (const float*)d_in[2];
    float* out = (float*)d_out;
    (void)in_sizes; (void)n_in; (void)out_size;

    tree_attn_kernel<<<(NBATCH * TT) / 4, 128>>>(q, k, v, out);
}

// round 13
// speedup vs baseline: 1.0015x; 1.0015x over previous
#include <cuda_runtime.h>
#include <stdint.h>

#define NBATCH 16
#define TT     2048
#define SS     2048
#define HH     64

typedef unsigned long long ull;

__device__ __forceinline__ ull umax64(ull a, ull b) { return a > b ? a : b; }
__device__ __forceinline__ ull umin64(ull a, ull b) { return a < b ? a : b; }

// key = (sortable_score << 8) | (127 - expanded_idx); numeric DESC order ==
// desc by score, ties by ascending index (replicates lax.top_k exactly,
// given equal pos -> bit-equal score).
__device__ __forceinline__ ull enc_key(float s, int idx) {
    unsigned u  = __float_as_uint(s);
    unsigned su = (u & 0x80000000u) ? ~u : (u | 0x80000000u);
    return ((ull)su << 8) | (ull)(127 - idx);
}
__device__ __forceinline__ float dec_score(ull k) {
    unsigned su = (unsigned)(k >> 8);
    unsigned u  = (su & 0x80000000u) ? (su & 0x7FFFFFFFu) : ~su;
    return __uint_as_float(u);
}

__global__ __launch_bounds__(128, 16)
void tree_attn_kernel(const float* __restrict__ q,
                      const float* __restrict__ kmat,
                      const float* __restrict__ v,
                      float* __restrict__ out)
{
    // per-warp private scratch (one row per warp; NO block barriers anywhere)
    __shared__ float              sc_s[4][66];   // scores by child slot (+pad)
    __shared__ int                zpar_s[4][64]; // parent z values
    __shared__ __align__(8) int2  fl_s[4][66];   // compacted fresh list (+pad)
    __shared__ __align__(16) ull  pk_s[4][64];   // epilogue (pos,p) packs

    const int wid  = threadIdx.x >> 5;
    const int lane = threadIdx.x & 31;
    const int row  = blockIdx.x * 4 + wid;
    const int n    = row >> 11;
    const int t    = row & (TT - 1);
    const float tsrc = (float)(t + 1);
    const int l16  = lane & 15;
    const int hw   = lane >> 4;          // half-warp 0/1
    const unsigned FULL = 0xffffffffu;
    const unsigned LT   = (1u << lane) - 1u;

    float* scw   = sc_s[wid];
    int*   zparw = zpar_s[wid];
    int2*  flw   = fl_s[wid];
    ull*   pkw   = pk_s[wid];

    const float* kbase = kmat + (size_t)n * SS * HH;
    const float4 q4 = ((const float4*)(q + ((size_t)(n * TT + t)) * HH))[l16];

    // R3-verbatim pinned scoring tree (bit-matches the reference einsum;
    // the reduction order must NOT change). 2 candidates per warp pass.
    #define SCORE2(PP, SLOT)                                                  \
        {                                                                     \
            const float4* krow = (const float4*)(kbase + (size_t)(PP) * HH);  \
            float4 k4 = krow[l16];                                            \
            float part = q4.x * k4.x + q4.y * k4.y + q4.z * k4.z + q4.w * k4.w;\
            part += __shfl_xor_sync(FULL, part, 1);                           \
            part += __shfl_xor_sync(FULL, part, 2);                           \
            part += __shfl_xor_sync(FULL, part, 4);                           \
            part += __shfl_xor_sync(FULL, part, 8);                           \
            if (l16 == 0) scw[SLOT] = part;                                   \
        }

    // ------------- it0: 32 fresh candidates (z = c), w2 = 32 ----------------
    ull key;
    {
        const float r = tsrc * (1.0f / 32.0f);
        #pragma unroll
        for (int j = 0; j < 16; ++j) {
            int c  = 2 * j + hw;
            int pp = min((int)rintf((float)c * r), SS - 1);
            SCORE2(pp, c)
        }
        __syncwarp();
        key = enc_key(scw[lane], lane);      // idx == z at level 0
        #pragma unroll
        for (int kk = 2; kk <= 32; kk <<= 1)
            #pragma unroll
            for (int j2 = kk >> 1; j2 > 0; j2 >>= 1) {
                ull p = __shfl_xor_sync(FULL, key, j2);
                bool mx = (((lane & j2) == 0) == ((lane & kk) == 0));
                key = mx ? umax64(key, p) : umin64(key, p);
            }
    }

    // 2-packed state: E0/E1 = kept keys at slots 2t/2t+1; zp0/zp1 parent z.
    // it0 kept 32 -> pad slots 32..63 with key 0 (below any real key).
    ull E0, E1; int zp0, zp1;
    {
        ull k0 = __shfl_sync(FULL, key, (2 * lane) & 31);
        ull k1 = __shfl_sync(FULL, key, (2 * lane + 1) & 31);
        bool lo = lane < 16;
        E0 = lo ? k0 : 0ull;
        E1 = lo ? k1 : 0ull;
        zp0 = lo ? (127 - (int)(k0 & 0xFF)) : 0;
        zp1 = lo ? (127 - (int)(k1 & 0xFF)) : 0;
    }

    // ------------- levels it = 1..6 (it1: 32 parents, else 64) --------------
    #pragma unroll 1
    for (int it = 1; it < 7; ++it) {
        const int   nPar = (it == 1) ? 32 : 64;
        const float r    = tsrc / (float)(32 << it);
        const int   a0   = 2 * lane, a1 = 2 * lane + 1;   // parent ranks

        // per-candidate collision skip: odd child landing on the even
        // sibling's token has a score bit-equal to the parent's -> inherit.
        int pE0 = min((int)rintf((float)(2 * zp0) * r),     SS - 1);
        int pO0 = min((int)rintf((float)(2 * zp0 + 1) * r), SS - 1);
        int pE1 = min((int)rintf((float)(2 * zp1) * r),     SS - 1);
        int pO1 = min((int)rintf((float)(2 * zp1 + 1) * r), SS - 1);
        bool real0 = a0 < nPar;
        bool real1 = a1 < nPar;
        bool fresh0 = real0 && (pO0 != pE0);
        bool fresh1 = real1 && (pO1 != pE1);

        if (real0 && (!fresh0 || !fresh1)) {
            // write inherited scores (pair store when both inherit)
            if (!fresh0 && !fresh1 && real1) {
                *(float2*)(scw + a0) = make_float2(dec_score(E0), dec_score(E1));
            } else {
                if (!fresh0)          scw[a0] = dec_score(E0);
                if (real1 && !fresh1) scw[a1] = dec_score(E1);
            }
        }
        *(int2*)(zparw + a0) = make_int2(zp0, zp1);

        // compact fresh candidates into a dense worklist (pos, slot)
        unsigned m0 = __ballot_sync(FULL, fresh0);
        unsigned m1 = __ballot_sync(FULL, fresh1);
        int c0 = __popc(m0);
        int nF = c0 + __popc(m1);
        if (fresh0) flw[__popc(m0 & LT)]      = make_int2(pO0, a0);
        if (fresh1) flw[c0 + __popc(m1 & LT)] = make_int2(pO1, a1);
        if (lane == 0) flw[nF] = make_int2(0, 64);   // pad entry -> scw[64]
        __syncwarp();

        // uniform scoring passes over the compacted list (2 per pass)
        for (int j = 0; j < nF; j += 2) {
            int2 ent = flw[j + hw];
            SCORE2(ent.x, ent.y)
        }
        __syncwarp();

        // odd keys 2/lane (expanded idx = 2*rank+1); pads -> 0
        float2 sc2 = *(const float2*)(scw + a0);     // one LDS.64
        ull O0 = real0 ? enc_key(sc2.x, 2 * a0 + 1) : 0ull;
        ull O1 = real1 ? enc_key(sc2.y, 2 * a1 + 1) : 0ull;

        // desc bitonic sort of 64 odds, 2/lane (R8/R9-validated network)
        #pragma unroll
        for (int kk = 2; kk <= 64; kk <<= 1) {
            #pragma unroll
            for (int j2 = kk >> 1; j2 > 0; j2 >>= 1) {
                bool grp0 = ((a0 & kk) == 0);
                if (j2 == 1) {
                    ull mxv = umax64(O0, O1), mnv = umin64(O0, O1);
                    O0 = grp0 ? mxv : mnv;
                    O1 = grp0 ? mnv : mxv;
                } else {
                    int jh = j2 >> 1;
                    ull b0 = __shfl_xor_sync(FULL, O0, jh);
                    ull b1 = __shfl_xor_sync(FULL, O1, jh);
                    bool mx = (((lane & jh) == 0) == grp0);
                    O0 = mx ? umax64(O0, b0) : umin64(O0, b0);
                    O1 = mx ? umax64(O1, b1) : umin64(O1, b1);
                }
            }
        }

        // combine: evens (sorted, reindexed to idx 2*slot) vs reversed odds
        ull rev0 = __shfl_sync(FULL, O1, 31 - lane);
        ull rev1 = __shfl_sync(FULL, O0, 31 - lane);
        E0 = (E0 & ~0xFFull) | (ull)(127 - 4 * lane);
        E1 = (E1 & ~0xFFull) | (ull)(127 - (4 * lane + 2));
        E0 = umax64(E0, rev0);              // top-64 multiset, bitonic
        E1 = umax64(E1, rev1);

        // 6-stage desc merge -> sorted (skipped at final level: epilogue is
        // set-order invariant — validated R6/R8/R9)
        if (it < 6) {
            #pragma unroll
            for (int j2 = 32; j2 > 1; j2 >>= 1) {
                int jh = j2 >> 1;
                ull b0 = __shfl_xor_sync(FULL, E0, jh);
                ull b1 = __shfl_xor_sync(FULL, E1, jh);
                bool mx = ((lane & jh) == 0);
                E0 = mx ? umax64(E0, b0) : umin64(E0, b0);
                E1 = mx ? umax64(E1, b1) : umin64(E1, b1);
            }
            ull mxv = umax64(E0, E1), mnv = umin64(E0, E1);
            E0 = mxv; E1 = mnv;
        }

        // decode next-level parents (zparw stable during this level)
        int e0 = 127 - (int)(E0 & 0xFF);
        int e1 = 127 - (int)(E1 & 0xFF);
        zp0 = 2 * zparw[e0 >> 1] + (e0 & 1);
        zp1 = 2 * zparw[e1 >> 1] + (e1 & 1);
    }

    // ------------- final attention over the 64 kept (warp-local) ------------
    {
        const float rf = tsrc * (1.0f / 2048.0f);
        int pos0 = min((int)rintf((float)zp0 * rf), SS - 1);
        int pos1 = min((int)rintf((float)zp1 * rf), SS - 1);
        bool v0 = ((float)pos0 < tsrc);
        bool v1 = ((float)pos1 < tsrc);
        float a0 = v0 ? dec_score(E0) * 0.125f : -1e9f;   // 1/sqrt(64)
        float a1 = v1 ? dec_score(E1) * 0.125f : -1e9f;

        float m = fmaxf(a0, a1);
        m = fmaxf(m, __shfl_xor_sync(FULL, m, 16));
        m = fmaxf(m, __shfl_xor_sync(FULL, m, 8));
        m = fmaxf(m, __shfl_xor_sync(FULL, m, 4));
        m = fmaxf(m, __shfl_xor_sync(FULL, m, 2));
        m = fmaxf(m, __shfl_xor_sync(FULL, m, 1));

        float e0 = v0 ? expf(a0 - m) : 0.0f;   // invalid: ref underflows to 0
        float e1 = v1 ? expf(a1 - m) : 0.0f;
        float s = e0 + e1;
        s += __shfl_xor_sync(FULL, s, 16);
        s += __shfl_xor_sync(FULL, s, 8);
        s += __shfl_xor_sync(FULL, s, 4);
        s += __shfl_xor_sync(FULL, s, 2);
        s += __shfl_xor_sync(FULL, s, 1);

        float p0 = (s > 0.0f) ? (e0 / s) : 0.0f;  // all-invalid -> 0 (ref)
        float p1 = (s > 0.0f) ? (e1 / s) : 0.0f;

        // pack (pos, p) per slot; one STS.128 per lane
        ull pk0 = ((ull)(unsigned)pos0 << 32) | __float_as_uint(p0);
        ull pk1 = ((ull)(unsigned)pos1 << 32) | __float_as_uint(p1);
        ((ulonglong2*)pkw)[lane] = make_ulonglong2(pk0, pk1);
        __syncwarp();

        // split gather: lanes 0-15 accumulate even entries, 16-31 odd entries;
        // each lane owns 4 h-values (float4 loads -> LDG.128, half the LDGs).
        const int hb = 4 * l16;
        const float* vb = v + (size_t)n * SS * HH + hb;
        float4 acc = make_float4(0.f, 0.f, 0.f, 0.f);
        #pragma unroll 8
        for (int kk = hw; kk < 64; kk += 2) {
            ull pv = pkw[kk];                 // LDS.64 broadcast per half
            int   pos = (int)(pv >> 32);
            float p   = __uint_as_float((unsigned)pv);
            float4 v4 = *(const float4*)(vb + (size_t)pos * HH);
            acc.x = fmaf(p, v4.x, acc.x);
            acc.y = fmaf(p, v4.y, acc.y);
            acc.z = fmaf(p, v4.z, acc.z);
            acc.w = fmaf(p, v4.w, acc.w);
        }
        // cross-half combine (even-partial + odd-partial)
        acc.x += __shfl_xor_sync(FULL, acc.x, 16);
        acc.y += __shfl_xor_sync(FULL, acc.y, 16);
        acc.z += __shfl_xor_sync(FULL, acc.z, 16);
        acc.w += __shfl_xor_sync(FULL, acc.w, 16);
        if (lane < 16)
            ((float4*)(out + ((size_t)(n * TT + t)) * HH))[l16] = acc;
    }
    #undef SCORE2
}

extern "C" void kernel_launch(void* const* d_in, const int* in_sizes, int n_in,
                              void* d_out, int out_size)
{
    const float* q = (const float*)d_in[0];
    const float* k = (const float*)d_in[1];
    const float* v = (const float*)d_in[2];
    float* out = (float*)d_out;
    (void)in_sizes; (void)n_in; (void)out_size;

    tree_attn_kernel<<<(NBATCH * TT) / 4, 128>>>(q, k, v, out);
}

// round 14
// speedup vs baseline: 1.0796x; 1.0780x over previous
#include <cuda_runtime.h>
#include <stdint.h>

#define NBATCH 16
#define TT     2048
#define SS     2048
#define HH     64

typedef unsigned long long ull;

__device__ __forceinline__ ull umax64(ull a, ull b) { return a > b ? a : b; }
__device__ __forceinline__ ull umin64(ull a, ull b) { return a < b ? a : b; }

// key = (sortable_score << 8) | (127 - expanded_idx); numeric DESC order ==
// desc by score, ties by ascending index (replicates lax.top_k exactly,
// given equal pos -> bit-equal score).
__device__ __forceinline__ ull enc_key(float s, int idx) {
    unsigned u  = __float_as_uint(s);
    unsigned su = (u & 0x80000000u) ? ~u : (u | 0x80000000u);
    return ((ull)su << 8) | (ull)(127 - idx);
}
__device__ __forceinline__ float dec_score(ull k) {
    unsigned su = (unsigned)(k >> 8);
    unsigned u  = (su & 0x80000000u) ? (su & 0x7FFFFFFFu) : ~su;
    return __uint_as_float(u);
}

__global__ __launch_bounds__(128, 12)
void tree_attn_kernel(const float* __restrict__ q,
                      const float* __restrict__ kmat,
                      const float* __restrict__ v,
                      float* __restrict__ out)
{
    // per-warp private scratch (one row per warp; NO block barriers anywhere)
    __shared__ float              sc_s[4][68];   // scores by child slot (+pads)
    __shared__ int                zpar_s[4][64]; // parent z values
    __shared__ __align__(8) int2  fl_s[4][68];   // compacted fresh list (+pads)
    __shared__ __align__(16) ull  pk_s[4][64];   // epilogue (pos,p) packs

    const int wid  = threadIdx.x >> 5;
    const int lane = threadIdx.x & 31;
    const int row  = blockIdx.x * 4 + wid;
    const int n    = row >> 11;
    const int t    = row & (TT - 1);
    const float tsrc = (float)(t + 1);
    const int l8   = lane & 7;           // lane within 8-lane scoring group
    const int grp  = lane >> 3;          // scoring group 0..3
    const int hw   = lane >> 4;
    const unsigned FULL = 0xffffffffu;
    const unsigned LT   = (1u << lane) - 1u;

    float* scw   = sc_s[wid];
    int*   zparw = zpar_s[wid];
    int2*  flw   = fl_s[wid];
    ull*   pkw   = pk_s[wid];

    const float* kbase = kmat + (size_t)n * SS * HH;
    const float4* qrow = (const float4*)(q + ((size_t)(n * TT + t)) * HH);
    const float4 qA = qrow[2 * l8];       // chunks 2*l8, 2*l8+1: 8 contiguous h
    const float4 qB = qrow[2 * l8 + 1];

    // 8-lane scoring tree, bit-identical to the R3-pinned 16-lane tree:
    // pA/pB are the same per-float4 FMA-chain partials; pA+pB equals the old
    // xor-1 shuffle step (IEEE add is commutative); the remaining xor 1,2,4
    // over 8 lanes reproduces old xor 2,4,8 exactly. 4 candidates per pass.
    #define SCORE4(PP, SLOT)                                                  \
        {                                                                     \
            const float4* krow = (const float4*)(kbase + (size_t)(PP) * HH);  \
            float4 kA = krow[2 * l8];                                         \
            float4 kB = krow[2 * l8 + 1];                                     \
            float pA = qA.x * kA.x + qA.y * kA.y + qA.z * kA.z + qA.w * kA.w; \
            float pB = qB.x * kB.x + qB.y * kB.y + qB.z * kB.z + qB.w * kB.w; \
            float part = pA + pB;                                             \
            part += __shfl_xor_sync(FULL, part, 1);                           \
            part += __shfl_xor_sync(FULL, part, 2);                           \
            part += __shfl_xor_sync(FULL, part, 4);                           \
            if (l8 == 0) scw[SLOT] = part;                                    \
        }

    // ------------- it0: 32 fresh candidates (z = c), w2 = 32 ----------------
    ull key;
    {
        const float r = tsrc * (1.0f / 32.0f);
        #pragma unroll
        for (int j = 0; j < 8; ++j) {
            int c  = 4 * j + grp;
            int pp = min((int)rintf((float)c * r), SS - 1);
            SCORE4(pp, c)
        }
        __syncwarp();
        key = enc_key(scw[lane], lane);      // idx == z at level 0
        #pragma unroll
        for (int kk = 2; kk <= 32; kk <<= 1)
            #pragma unroll
            for (int j2 = kk >> 1; j2 > 0; j2 >>= 1) {
                ull p = __shfl_xor_sync(FULL, key, j2);
                bool mx = (((lane & j2) == 0) == ((lane & kk) == 0));
                key = mx ? umax64(key, p) : umin64(key, p);
            }
    }

    // 2-packed state: E0/E1 = kept keys at slots 2t/2t+1; zp0/zp1 parent z.
    // it0 kept 32 -> pad slots 32..63 with key 0 (below any real key).
    ull E0, E1; int zp0, zp1;
    {
        ull k0 = __shfl_sync(FULL, key, (2 * lane) & 31);
        ull k1 = __shfl_sync(FULL, key, (2 * lane + 1) & 31);
        bool lo = lane < 16;
        E0 = lo ? k0 : 0ull;
        E1 = lo ? k1 : 0ull;
        zp0 = lo ? (127 - (int)(k0 & 0xFF)) : 0;
        zp1 = lo ? (127 - (int)(k1 & 0xFF)) : 0;
    }

    // ------------- levels it = 1..6 (it1: 32 parents, else 64) --------------
    #pragma unroll 1
    for (int it = 1; it < 7; ++it) {
        const int   nPar = (it == 1) ? 32 : 64;
        const float r    = tsrc / (float)(32 << it);
        const int   a0   = 2 * lane, a1 = 2 * lane + 1;   // parent ranks

        // per-candidate collision skip: odd child landing on the even
        // sibling's token has a score bit-equal to the parent's -> inherit.
        int pE0 = min((int)rintf((float)(2 * zp0) * r),     SS - 1);
        int pO0 = min((int)rintf((float)(2 * zp0 + 1) * r), SS - 1);
        int pE1 = min((int)rintf((float)(2 * zp1) * r),     SS - 1);
        int pO1 = min((int)rintf((float)(2 * zp1 + 1) * r), SS - 1);
        bool real0 = a0 < nPar;
        bool real1 = a1 < nPar;
        bool fresh0 = real0 && (pO0 != pE0);
        bool fresh1 = real1 && (pO1 != pE1);

        if (real0 && (!fresh0 || !fresh1)) {
            if (!fresh0 && !fresh1 && real1) {
                *(float2*)(scw + a0) = make_float2(dec_score(E0), dec_score(E1));
            } else {
                if (!fresh0)          scw[a0] = dec_score(E0);
                if (real1 && !fresh1) scw[a1] = dec_score(E1);
            }
        }
        *(int2*)(zparw + a0) = make_int2(zp0, zp1);

        // compact fresh candidates into a dense worklist (pos, slot)
        unsigned m0 = __ballot_sync(FULL, fresh0);
        unsigned m1 = __ballot_sync(FULL, fresh1);
        int c0 = __popc(m0);
        int nF = c0 + __popc(m1);
        if (fresh0) flw[__popc(m0 & LT)]      = make_int2(pO0, a0);
        if (fresh1) flw[c0 + __popc(m1 & LT)] = make_int2(pO1, a1);
        if (lane < 3) flw[nF + lane] = make_int2(0, 64 + lane);  // pads
        __syncwarp();

        // uniform scoring passes over the compacted list (4 per pass)
        for (int j = 0; j < nF; j += 4) {
            int2 ent = flw[j + grp];
            SCORE4(ent.x, ent.y)
        }
        __syncwarp();

        // odd keys 2/lane (expanded idx = 2*rank+1); pads -> 0
        float2 sc2 = *(const float2*)(scw + a0);     // one LDS.64
        ull O0 = real0 ? enc_key(sc2.x, 2 * a0 + 1) : 0ull;
        ull O1 = real1 ? enc_key(sc2.y, 2 * a1 + 1) : 0ull;

        // desc bitonic sort of 64 odds, 2/lane (R8/R9-validated network)
        #pragma unroll
        for (int kk = 2; kk <= 64; kk <<= 1) {
            #pragma unroll
            for (int j2 = kk >> 1; j2 > 0; j2 >>= 1) {
                bool grp0 = ((a0 & kk) == 0);
                if (j2 == 1) {
                    ull mxv = umax64(O0, O1), mnv = umin64(O0, O1);
                    O0 = grp0 ? mxv : mnv;
                    O1 = grp0 ? mnv : mxv;
                } else {
                    int jh = j2 >> 1;
                    ull b0 = __shfl_xor_sync(FULL, O0, jh);
                    ull b1 = __shfl_xor_sync(FULL, O1, jh);
                    bool mx = (((lane & jh) == 0) == grp0);
                    O0 = mx ? umax64(O0, b0) : umin64(O0, b0);
                    O1 = mx ? umax64(O1, b1) : umin64(O1, b1);
                }
            }
        }

        // combine: evens (sorted, reindexed to idx 2*slot) vs reversed odds
        ull rev0 = __shfl_sync(FULL, O1, 31 - lane);
        ull rev1 = __shfl_sync(FULL, O0, 31 - lane);
        E0 = (E0 & ~0xFFull) | (ull)(127 - 4 * lane);
        E1 = (E1 & ~0xFFull) | (ull)(127 - (4 * lane + 2));
        E0 = umax64(E0, rev0);              // top-64 multiset, bitonic
        E1 = umax64(E1, rev1);

        // 6-stage desc merge -> sorted (skipped at final level: epilogue is
        // set-order invariant — validated R6/R8/R9)
        if (it < 6) {
            #pragma unroll
            for (int j2 = 32; j2 > 1; j2 >>= 1) {
                int jh = j2 >> 1;
                ull b0 = __shfl_xor_sync(FULL, E0, jh);
                ull b1 = __shfl_xor_sync(FULL, E1, jh);
                bool mx = ((lane & jh) == 0);
                E0 = mx ? umax64(E0, b0) : umin64(E0, b0);
                E1 = mx ? umax64(E1, b1) : umin64(E1, b1);
            }
            ull mxv = umax64(E0, E1), mnv = umin64(E0, E1);
            E0 = mxv; E1 = mnv;
        }

        // decode next-level parents (zparw stable during this level)
        int e0 = 127 - (int)(E0 & 0xFF);
        int e1 = 127 - (int)(E1 & 0xFF);
        zp0 = 2 * zparw[e0 >> 1] + (e0 & 1);
        zp1 = 2 * zparw[e1 >> 1] + (e1 & 1);
    }

    // ------------- final attention over the 64 kept (warp-local) ------------
    {
        const float rf = tsrc * (1.0f / 2048.0f);
        int pos0 = min((int)rintf((float)zp0 * rf), SS - 1);
        int pos1 = min((int)rintf((float)zp1 * rf), SS - 1);
        bool v0 = ((float)pos0 < tsrc);
        bool v1 = ((float)pos1 < tsrc);
        float a0 = v0 ? dec_score(E0) * 0.125f : -1e9f;   // 1/sqrt(64)
        float a1 = v1 ? dec_score(E1) * 0.125f : -1e9f;

        float m = fmaxf(a0, a1);
        m = fmaxf(m, __shfl_xor_sync(FULL, m, 16));
        m = fmaxf(m, __shfl_xor_sync(FULL, m, 8));
        m = fmaxf(m, __shfl_xor_sync(FULL, m, 4));
        m = fmaxf(m, __shfl_xor_sync(FULL, m, 2));
        m = fmaxf(m, __shfl_xor_sync(FULL, m, 1));

        float e0 = v0 ? expf(a0 - m) : 0.0f;   // invalid: ref underflows to 0
        float e1 = v1 ? expf(a1 - m) : 0.0f;
        float s = e0 + e1;
        s += __shfl_xor_sync(FULL, s, 16);
        s += __shfl_xor_sync(FULL, s, 8);
        s += __shfl_xor_sync(FULL, s, 4);
        s += __shfl_xor_sync(FULL, s, 2);
        s += __shfl_xor_sync(FULL, s, 1);

        float p0 = (s > 0.0f) ? (e0 / s) : 0.0f;  // all-invalid -> 0 (ref)
        float p1 = (s > 0.0f) ? (e1 / s) : 0.0f;

        // pack (pos, p) per slot; one STS.128 per lane
        ull pk0 = ((ull)(unsigned)pos0 << 32) | __float_as_uint(p0);
        ull pk1 = ((ull)(unsigned)pos1 << 32) | __float_as_uint(p1);
        ((ulonglong2*)pkw)[lane] = make_ulonglong2(pk0, pk1);
        __syncwarp();

        // R10-validated gather: thread pair-h layout, uint4 pack reads
        const float* vb = v + (size_t)n * SS * HH;
        float acc0 = 0.0f, acc1 = 0.0f;
        #pragma unroll 4
        for (int kk = 0; kk < 32; ++kk) {
            uint4 u = ((const uint4*)pkw)[kk];     // 2 packed entries
            float pa  = __uint_as_float(u.x);
            int   psa = (int)u.y;
            float pb  = __uint_as_float(u.z);
            int   psb = (int)u.w;
            float2 va = *(const float2*)(vb + (size_t)psa * HH + 2 * lane);
            acc0 = fmaf(pa, va.x, acc0);
            acc1 = fmaf(pa, va.y, acc1);
            float2 vbv = *(const float2*)(vb + (size_t)psb * HH + 2 * lane);
            acc0 = fmaf(pb, vbv.x, acc0);
            acc1 = fmaf(pb, vbv.y, acc1);
        }
        ((float2*)(out + ((size_t)(n * TT + t)) * HH))[lane] =
            make_float2(acc0, acc1);
    }
    #undef SCORE4
}

extern "C" void kernel_launch(void* const* d_in, const int* in_sizes, int n_in,
                              void* d_out, int out_size)
{
    const float* q = (const float*)d_in[0];
    const float* k = (const float*)d_in[1];
    const float* v = (const float*)d_in[2];
    float* out = (float*)d_out;
    (void)in_sizes; (void)n_in; (void)out_size;

    tree_attn_kernel<<<(NBATCH * TT) / 4, 128>>>(q, k, v, out);
}

// round 15
// speedup vs baseline: 1.1155x; 1.0332x over previous
#include <cuda_runtime.h>
#include <stdint.h>

#define NBATCH 16
#define TT     2048
#define SS     2048
#define HH     64

typedef unsigned long long ull;

__device__ __forceinline__ ull umax64(ull a, ull b) { return a > b ? a : b; }
__device__ __forceinline__ ull umin64(ull a, ull b) { return a < b ? a : b; }

// key = (sortable_score << 8) | (127 - expanded_idx); numeric DESC order ==
// desc by score, ties by ascending index (replicates lax.top_k exactly,
// given equal pos -> bit-equal score).
__device__ __forceinline__ ull enc_key(float s, int idx) {
    unsigned u  = __float_as_uint(s);
    unsigned su = (u & 0x80000000u) ? ~u : (u | 0x80000000u);
    return ((ull)su << 8) | (ull)(127 - idx);
}
__device__ __forceinline__ float dec_score(ull k) {
    unsigned su = (unsigned)(k >> 8);
    unsigned u  = (su & 0x80000000u) ? (su & 0x7FFFFFFFu) : ~su;
    return __uint_as_float(u);
}

__global__ __launch_bounds__(128, 12)
void tree_attn_kernel(const float* __restrict__ q,
                      const float* __restrict__ kmat,
                      const float* __restrict__ v,
                      float* __restrict__ out)
{
    // per-warp private scratch (one row per warp; NO block barriers anywhere)
    __shared__ float              sc_s[4][68];   // fresh scores by child slot
    __shared__ int                zpar_s[4][64]; // parent z values
    __shared__ __align__(8) int2  fl_s[4][68];   // compacted fresh list (+pads)
    __shared__ __align__(16) ull  pk_s[4][64];   // epilogue (pos,p) packs

    const int wid  = threadIdx.x >> 5;
    const int lane = threadIdx.x & 31;
    const int row  = blockIdx.x * 4 + wid;
    const int n    = row >> 11;
    const int t    = row & (TT - 1);
    const float tsrc = (float)(t + 1);
    const int l8   = lane & 7;           // lane within 8-lane scoring group
    const int grp  = lane >> 3;          // scoring group 0..3
    const unsigned FULL = 0xffffffffu;
    const unsigned LT   = (1u << lane) - 1u;

    float* scw   = sc_s[wid];
    int*   zparw = zpar_s[wid];
    int2*  flw   = fl_s[wid];
    ull*   pkw   = pk_s[wid];

    const float* kbase = kmat + (size_t)n * SS * HH;
    const float4* qrow = (const float4*)(q + ((size_t)(n * TT + t)) * HH);
    const float4 qA = qrow[l8];       // chunk l8      (row line 0)
    const float4 qB = qrow[l8 + 8];   // chunk l8 + 8  (row line 1)

    // Bit-identical rebuild of the pinned R3 reduction DAG with line-clean
    // loads: kA touches only line 0 of the key row, kB only line 1 (1 line
    // per row per LDG warp-op). Two parallel 8-leaf trees:
    //   u: xor1->a, xor2->b, xor4->d0 over chunks 0..7
    //   w: same over chunks 8..15 -> d8;  part = d0 + d8 (R3's xor8 top).
    // All intermediates bit-equal to R3 by IEEE add commutativity.
    // 4 candidates per warp pass.
    #define SCORE4(PP, SLOT)                                                  \
        {                                                                     \
            const float4* krow = (const float4*)(kbase + (size_t)(PP) * HH);  \
            float4 kA = krow[l8];                                             \
            float4 kB = krow[l8 + 8];                                         \
            float u = qA.x * kA.x + qA.y * kA.y + qA.z * kA.z + qA.w * kA.w;  \
            float w = qB.x * kB.x + qB.y * kB.y + qB.z * kB.z + qB.w * kB.w;  \
            u += __shfl_xor_sync(FULL, u, 1);                                 \
            w += __shfl_xor_sync(FULL, w, 1);                                 \
            u += __shfl_xor_sync(FULL, u, 2);                                 \
            w += __shfl_xor_sync(FULL, w, 2);                                 \
            u += __shfl_xor_sync(FULL, u, 4);                                 \
            w += __shfl_xor_sync(FULL, w, 4);                                 \
            float part = u + w;                                               \
            if (l8 == 0) scw[SLOT] = part;                                    \
        }

    // ------------- it0: 32 fresh candidates (z = c), w2 = 32 ----------------
    ull key;
    {
        const float r = tsrc * (1.0f / 32.0f);
        #pragma unroll
        for (int j = 0; j < 8; ++j) {
            int c  = 4 * j + grp;
            int pp = min((int)rintf((float)c * r), SS - 1);
            SCORE4(pp, c)
        }
        __syncwarp();
        key = enc_key(scw[lane], lane);      // idx == z at level 0
        #pragma unroll
        for (int kk = 2; kk <= 32; kk <<= 1)
            #pragma unroll
            for (int j2 = kk >> 1; j2 > 0; j2 >>= 1) {
                ull p = __shfl_xor_sync(FULL, key, j2);
                bool mx = (((lane & j2) == 0) == ((lane & kk) == 0));
                key = mx ? umax64(key, p) : umin64(key, p);
            }
    }

    // 2-packed state: E0/E1 = kept keys at slots 2t/2t+1; zp0/zp1 parent z.
    // it0 kept 32 -> pad slots 32..63 with key 0 (below any real key).
    ull E0, E1; int zp0, zp1;
    {
        ull k0 = __shfl_sync(FULL, key, (2 * lane) & 31);
        ull k1 = __shfl_sync(FULL, key, (2 * lane + 1) & 31);
        bool lo = lane < 16;
        E0 = lo ? k0 : 0ull;
        E1 = lo ? k1 : 0ull;
        zp0 = lo ? (127 - (int)(k0 & 0xFF)) : 0;
        zp1 = lo ? (127 - (int)(k1 & 0xFF)) : 0;
    }

    // ------------- levels it = 1..6 (it1: 32 parents, else 64) --------------
    #pragma unroll 1
    for (int it = 1; it < 7; ++it) {
        const int   nPar = (it == 1) ? 32 : 64;
        const float r    = tsrc / (float)(32 << it);
        const int   a0   = 2 * lane, a1 = 2 * lane + 1;   // parent ranks

        // per-candidate collision skip: odd child landing on the even
        // sibling's token has a score bit-equal to the parent's -> inherit
        // the key bits directly in-register (idx byte swapped).
        int pE0 = min((int)rintf((float)(2 * zp0) * r),     SS - 1);
        int pO0 = min((int)rintf((float)(2 * zp0 + 1) * r), SS - 1);
        int pE1 = min((int)rintf((float)(2 * zp1) * r),     SS - 1);
        int pO1 = min((int)rintf((float)(2 * zp1 + 1) * r), SS - 1);
        bool real0 = a0 < nPar;
        bool real1 = a1 < nPar;
        bool fresh0 = real0 && (pO0 != pE0);
        bool fresh1 = real1 && (pO1 != pE1);

        *(int2*)(zparw + a0) = make_int2(zp0, zp1);

        // compact fresh candidates into a dense worklist (pos, slot)
        unsigned m0 = __ballot_sync(FULL, fresh0);
        unsigned m1 = __ballot_sync(FULL, fresh1);
        int c0 = __popc(m0);
        int nF = c0 + __popc(m1);
        if (fresh0) flw[__popc(m0 & LT)]      = make_int2(pO0, a0);
        if (fresh1) flw[c0 + __popc(m1 & LT)] = make_int2(pO1, a1);
        if (lane < 3) flw[nF + lane] = make_int2(0, 64 + lane);  // pads
        __syncwarp();

        // uniform scoring passes over the compacted list (4 per pass)
        for (int j = 0; j < nF; j += 4) {
            int2 ent = flw[j + grp];
            SCORE4(ent.x, ent.y)
        }
        __syncwarp();

        // odd keys 2/lane (expanded idx = 2*rank+1); inherited odds reuse the
        // parent's score bits in-register; pads -> 0
        float2 sc2 = *(const float2*)(scw + a0);     // one LDS.64 (fresh vals)
        ull O0 = !real0 ? 0ull
               : (fresh0 ? enc_key(sc2.x, 2 * a0 + 1)
                         : ((E0 & ~0xFFull) | (ull)(127 - (2 * a0 + 1))));
        ull O1 = !real1 ? 0ull
               : (fresh1 ? enc_key(sc2.y, 2 * a1 + 1)
                         : ((E1 & ~0xFFull) | (ull)(127 - (2 * a1 + 1))));

        // desc bitonic sort of 64 odds, 2/lane (R8/R9-validated network)
        #pragma unroll
        for (int kk = 2; kk <= 64; kk <<= 1) {
            #pragma unroll
            for (int j2 = kk >> 1; j2 > 0; j2 >>= 1) {
                bool grp0 = ((a0 & kk) == 0);
                if (j2 == 1) {
                    ull mxv = umax64(O0, O1), mnv = umin64(O0, O1);
                    O0 = grp0 ? mxv : mnv;
                    O1 = grp0 ? mnv : mxv;
                } else {
                    int jh = j2 >> 1;
                    ull b0 = __shfl_xor_sync(FULL, O0, jh);
                    ull b1 = __shfl_xor_sync(FULL, O1, jh);
                    bool mx = (((lane & jh) == 0) == grp0);
                    O0 = mx ? umax64(O0, b0) : umin64(O0, b0);
                    O1 = mx ? umax64(O1, b1) : umin64(O1, b1);
                }
            }
        }

        // combine: evens (sorted, reindexed to idx 2*slot) vs reversed odds
        ull rev0 = __shfl_sync(FULL, O1, 31 - lane);
        ull rev1 = __shfl_sync(FULL, O0, 31 - lane);
        E0 = (E0 & ~0xFFull) | (ull)(127 - 4 * lane);
        E1 = (E1 & ~0xFFull) | (ull)(127 - (4 * lane + 2));
        E0 = umax64(E0, rev0);              // top-64 multiset, bitonic
        E1 = umax64(E1, rev1);

        // 6-stage desc merge -> sorted (skipped at final level: epilogue is
        // set-order invariant — validated R6/R8/R9)
        if (it < 6) {
            #pragma unroll
            for (int j2 = 32; j2 > 1; j2 >>= 1) {
                int jh = j2 >> 1;
                ull b0 = __shfl_xor_sync(FULL, E0, jh);
                ull b1 = __shfl_xor_sync(FULL, E1, jh);
                bool mx = ((lane & jh) == 0);
                E0 = mx ? umax64(E0, b0) : umin64(E0, b0);
                E1 = mx ? umax64(E1, b1) : umin64(E1, b1);
            }
            ull mxv = umax64(E0, E1), mnv = umin64(E0, E1);
            E0 = mxv; E1 = mnv;
        }

        // decode next-level parents (zparw stable during this level)
        int e0 = 127 - (int)(E0 & 0xFF);
        int e1 = 127 - (int)(E1 & 0xFF);
        zp0 = 2 * zparw[e0 >> 1] + (e0 & 1);
        zp1 = 2 * zparw[e1 >> 1] + (e1 & 1);
    }

    // ------------- final attention over the 64 kept (warp-local) ------------
    {
        const float rf = tsrc * (1.0f / 2048.0f);
        int pos0 = min((int)rintf((float)zp0 * rf), SS - 1);
        int pos1 = min((int)rintf((float)zp1 * rf), SS - 1);
        bool v0 = ((float)pos0 < tsrc);
        bool v1 = ((float)pos1 < tsrc);
        float a0 = v0 ? dec_score(E0) * 0.125f : -1e9f;   // 1/sqrt(64)
        float a1 = v1 ? dec_score(E1) * 0.125f : -1e9f;

        float m = fmaxf(a0, a1);
        m = fmaxf(m, __shfl_xor_sync(FULL, m, 16));
        m = fmaxf(m, __shfl_xor_sync(FULL, m, 8));
        m = fmaxf(m, __shfl_xor_sync(FULL, m, 4));
        m = fmaxf(m, __shfl_xor_sync(FULL, m, 2));
        m = fmaxf(m, __shfl_xor_sync(FULL, m, 1));

        float e0 = v0 ? expf(a0 - m) : 0.0f;   // invalid: ref underflows to 0
        float e1 = v1 ? expf(a1 - m) : 0.0f;
        float s = e0 + e1;
        s += __shfl_xor_sync(FULL, s, 16);
        s += __shfl_xor_sync(FULL, s, 8);
        s += __shfl_xor_sync(FULL, s, 4);
        s += __shfl_xor_sync(FULL, s, 2);
        s += __shfl_xor_sync(FULL, s, 1);

        float p0 = (s > 0.0f) ? (e0 / s) : 0.0f;  // all-invalid -> 0 (ref)
        float p1 = (s > 0.0f) ? (e1 / s) : 0.0f;

        // pack (pos, p) per slot; one STS.128 per lane
        ull pk0 = ((ull)(unsigned)pos0 << 32) | __float_as_uint(p0);
        ull pk1 = ((ull)(unsigned)pos1 << 32) | __float_as_uint(p1);
        ((ulonglong2*)pkw)[lane] = make_ulonglong2(pk0, pk1);
        __syncwarp();

        // R10-validated gather: thread pair-h layout, uint4 pack reads
        const float* vb = v + (size_t)n * SS * HH;
        float acc0 = 0.0f, acc1 = 0.0f;
        #pragma unroll 4
        for (int kk = 0; kk < 32; ++kk) {
            uint4 u = ((const uint4*)pkw)[kk];     // 2 packed entries
            float pa  = __uint_as_float(u.x);
            int   psa = (int)u.y;
            float pb  = __uint_as_float(u.z);
            int   psb = (int)u.w;
            float2 va = *(const float2*)(vb + (size_t)psa * HH + 2 * lane);
            acc0 = fmaf(pa, va.x, acc0);
            acc1 = fmaf(pa, va.y, acc1);
            float2 vbv = *(const float2*)(vb + (size_t)psb * HH + 2 * lane);
            acc0 = fmaf(pb, vbv.x, acc0);
            acc1 = fmaf(pb, vbv.y, acc1);
        }
        ((float2*)(out + ((size_t)(n * TT + t)) * HH))[lane] =
            make_float2(acc0, acc1);
    }
    #undef SCORE4
}

extern "C" void kernel_launch(void* const* d_in, const int* in_sizes, int n_in,
                              void* d_out, int out_size)
{
    const float* q = (const float*)d_in[0];
    const float* k = (const float*)d_in[1];
    const float* v = (const float*)d_in[2];
    float* out = (float*)d_out;
    (void)in_sizes; (void)n_in; (void)out_size;

    tree_attn_kernel<<<(NBATCH * TT) / 4, 128>>>(q, k, v, out);
}

// round 16
// speedup vs baseline: 1.1411x; 1.0230x over previous
#include <cuda_runtime.h>
#include <stdint.h>

#define NBATCH 16
#define TT     2048
#define SS     2048
#define HH     64

typedef unsigned long long ull;

__device__ __forceinline__ ull umax64(ull a, ull b) { return a > b ? a : b; }
__device__ __forceinline__ ull umin64(ull a, ull b) { return a < b ? a : b; }

// key = (sortable_score << 8) | (127 - expanded_idx); numeric DESC order ==
// desc by score, ties by ascending index (replicates lax.top_k exactly,
// given equal pos -> bit-equal score).
__device__ __forceinline__ ull enc_key(float s, int idx) {
    unsigned u  = __float_as_uint(s);
    unsigned su = (u & 0x80000000u) ? ~u : (u | 0x80000000u);
    return ((ull)su << 8) | (ull)(127 - idx);
}
__device__ __forceinline__ float dec_score(ull k) {
    unsigned su = (unsigned)(k >> 8);
    unsigned u  = (su & 0x80000000u) ? (su & 0x7FFFFFFFu) : ~su;
    return __uint_as_float(u);
}

__global__ __launch_bounds__(64, 25)
void tree_attn_kernel(const float* __restrict__ q,
                      const float* __restrict__ kmat,
                      const float* __restrict__ v,
                      float* __restrict__ out)
{
    // per-warp private scratch (one row per warp; NO block barriers anywhere)
    __shared__ float              sc_s[2][68];   // fresh scores by child slot
    __shared__ int                zpar_s[2][64]; // parent z values
    __shared__ __align__(8) int2  fl_s[2][68];   // compacted fresh list (+pads)
    __shared__ __align__(16) ull  pk_s[2][64];   // epilogue (pos,p) packs

    const int wid  = threadIdx.x >> 5;
    const int lane = threadIdx.x & 31;
    const int row  = blockIdx.x * 2 + wid;
    const int n    = row >> 11;
    const int t    = row & (TT - 1);
    const float tsrc = (float)(t + 1);
    const int l8   = lane & 7;           // lane within 8-lane scoring group
    const int grp  = lane >> 3;          // scoring group 0..3
    const unsigned FULL = 0xffffffffu;
    const unsigned LT   = (1u << lane) - 1u;

    float* scw   = sc_s[wid];
    int*   zparw = zpar_s[wid];
    int2*  flw   = fl_s[wid];
    ull*   pkw   = pk_s[wid];

    const float* kbase = kmat + (size_t)n * SS * HH;
    const float4* qrow = (const float4*)(q + ((size_t)(n * TT + t)) * HH);
    const float4 qA = qrow[l8];       // chunk l8      (row line 0)
    const float4 qB = qrow[l8 + 8];   // chunk l8 + 8  (row line 1)

    // R14-validated line-clean rebuild of the pinned R3 reduction DAG:
    // kA touches only line 0 of the key row, kB only line 1. Two parallel
    // 8-leaf trees; part = d0 + d8. Bit-equal to R3 by IEEE commutativity.
    // 4 candidates per warp pass.
    #define SCORE4(PP, SLOT)                                                  \
        {                                                                     \
            const float4* krow = (const float4*)(kbase + (size_t)(PP) * HH);  \
            float4 kA = krow[l8];                                             \
            float4 kB = krow[l8 + 8];                                         \
            float u = qA.x * kA.x + qA.y * kA.y + qA.z * kA.z + qA.w * kA.w;  \
            float w = qB.x * kB.x + qB.y * kB.y + qB.z * kB.z + qB.w * kB.w;  \
            u += __shfl_xor_sync(FULL, u, 1);                                 \
            w += __shfl_xor_sync(FULL, w, 1);                                 \
            u += __shfl_xor_sync(FULL, u, 2);                                 \
            w += __shfl_xor_sync(FULL, w, 2);                                 \
            u += __shfl_xor_sync(FULL, u, 4);                                 \
            w += __shfl_xor_sync(FULL, w, 4);                                 \
            float part = u + w;                                               \
            if (l8 == 0) scw[SLOT] = part;                                    \
        }

    // ------------- it0: 32 fresh candidates (z = c), w2 = 32 ----------------
    ull key;   // after it0: lane = rank, sorted desc
    {
        const float r = tsrc * (1.0f / 32.0f);
        #pragma unroll
        for (int j = 0; j < 8; ++j) {
            int c  = 4 * j + grp;
            int pp = min((int)rintf((float)c * r), SS - 1);
            SCORE4(pp, c)
        }
        __syncwarp();
        key = enc_key(scw[lane], lane);      // idx == z at level 0
        #pragma unroll
        for (int kk = 2; kk <= 32; kk <<= 1)
            #pragma unroll
            for (int j2 = kk >> 1; j2 > 0; j2 >>= 1) {
                ull p = __shfl_xor_sync(FULL, key, j2);
                bool mx = (((lane & j2) == 0) == ((lane & kk) == 0));
                key = mx ? umax64(key, p) : umin64(key, p);
            }
    }

    ull E0, E1;      // kept keys at slots 2t/2t+1 (2-packed state)
    int zp0, zp1;    // parent z at slots 2t/2t+1

    // ------------- it1 special: 32 parents -> keep all 64, w2 = 64 ----------
    {
        const float r = tsrc * (1.0f / 64.0f);
        int zpar1 = 127 - (int)(key & 0xFF);  // parent z, rank = lane
        int pE = min((int)rintf((float)(2 * zpar1) * r),     SS - 1);
        int pO = min((int)rintf((float)(2 * zpar1 + 1) * r), SS - 1);
        bool fresh = (pO != pE);
        zparw[lane] = zpar1;

        unsigned m = __ballot_sync(FULL, fresh);
        int nF = __popc(m);
        if (fresh) flw[__popc(m & LT)] = make_int2(pO, lane);
        if (lane < 3) flw[nF + lane] = make_int2(0, 64 + lane);  // pads
        __syncwarp();
        for (int j = 0; j < nF; j += 4) {
            int2 ent = flw[j + grp];
            SCORE4(ent.x, ent.y)
        }
        __syncwarp();

        // odd key per lane (rank = lane): fresh score or inherited key bits
        ull okey = fresh ? enc_key(scw[lane], 2 * lane + 1)
                         : ((key & ~0xFFull) | (ull)(127 - (2 * lane + 1)));
        // 15-stage desc bitonic sort of the 32 odds (1 key/lane)
        #pragma unroll
        for (int kk = 2; kk <= 32; kk <<= 1)
            #pragma unroll
            for (int j2 = kk >> 1; j2 > 0; j2 >>= 1) {
                ull p = __shfl_xor_sync(FULL, okey, j2);
                bool mx = (((lane & j2) == 0) == ((lane & kk) == 0));
                okey = mx ? umax64(okey, p) : umin64(okey, p);
            }

        // distribute into 2-packed slot space: [32 real desc | 32 zeros]
        ull O0 = __shfl_sync(FULL, okey, (2 * lane) & 31);
        ull O1 = __shfl_sync(FULL, okey, (2 * lane + 1) & 31);
        ull k0e = __shfl_sync(FULL, key, (2 * lane) & 31);
        ull k1e = __shfl_sync(FULL, key, (2 * lane + 1) & 31);
        bool lo = lane < 16;
        if (!lo) { O0 = 0ull; O1 = 0ull; }
        // evens: parent rank 2t -> expanded idx 4t (pads zero)
        E0 = lo ? ((k0e & ~0xFFull) | (ull)(127 - 4 * lane)) : 0ull;
        E1 = lo ? ((k1e & ~0xFFull) | (ull)(127 - (4 * lane + 2))) : 0ull;

        // combine + full 6-stage desc merge -> all 64 kept, sorted
        ull rev0 = __shfl_sync(FULL, O1, 31 - lane);
        ull rev1 = __shfl_sync(FULL, O0, 31 - lane);
        E0 = umax64(E0, rev0);
        E1 = umax64(E1, rev1);
        #pragma unroll
        for (int j2 = 32; j2 > 1; j2 >>= 1) {
            int jh = j2 >> 1;
            ull b0 = __shfl_xor_sync(FULL, E0, jh);
            ull b1 = __shfl_xor_sync(FULL, E1, jh);
            bool mx = ((lane & jh) == 0);
            E0 = mx ? umax64(E0, b0) : umin64(E0, b0);
            E1 = mx ? umax64(E1, b1) : umin64(E1, b1);
        }
        ull mxv = umax64(E0, E1), mnv = umin64(E0, E1);
        E0 = mxv; E1 = mnv;

        int e0 = 127 - (int)(E0 & 0xFF);
        int e1 = 127 - (int)(E1 & 0xFF);
        zp0 = 2 * zparw[e0 >> 1] + (e0 & 1);
        zp1 = 2 * zparw[e1 >> 1] + (e1 & 1);
    }

    // ------------- levels it = 2..6: 64 parents -> top-64 of 128 ------------
    #pragma unroll 1
    for (int it = 2; it < 7; ++it) {
        const float r  = tsrc / (float)(32 << it);
        const int   a0 = 2 * lane, a1 = 2 * lane + 1;   // parent ranks

        // per-candidate collision skip: odd child landing on the even
        // sibling's token has a score bit-equal to the parent's -> inherit
        // the key bits directly in-register (idx byte swapped).
        int pE0 = min((int)rintf((float)(2 * zp0) * r),     SS - 1);
        int pO0 = min((int)rintf((float)(2 * zp0 + 1) * r), SS - 1);
        int pE1 = min((int)rintf((float)(2 * zp1) * r),     SS - 1);
        int pO1 = min((int)rintf((float)(2 * zp1 + 1) * r), SS - 1);
        bool fresh0 = (pO0 != pE0);
        bool fresh1 = (pO1 != pE1);

        *(int2*)(zparw + a0) = make_int2(zp0, zp1);

        // compact fresh candidates into a dense worklist (pos, slot)
        unsigned m0 = __ballot_sync(FULL, fresh0);
        unsigned m1 = __ballot_sync(FULL, fresh1);
        int c0 = __popc(m0);
        int nF = c0 + __popc(m1);
        if (fresh0) flw[__popc(m0 & LT)]      = make_int2(pO0, a0);
        if (fresh1) flw[c0 + __popc(m1 & LT)] = make_int2(pO1, a1);
        if (lane < 3) flw[nF + lane] = make_int2(0, 64 + lane);  // pads
        __syncwarp();

        // uniform scoring passes over the compacted list (4 per pass)
        for (int j = 0; j < nF; j += 4) {
            int2 ent = flw[j + grp];
            SCORE4(ent.x, ent.y)
        }
        __syncwarp();

        // odd keys 2/lane (expanded idx = 2*rank+1); inherited odds reuse the
        // parent's score bits in-register
        float2 sc2 = *(const float2*)(scw + a0);     // one LDS.64 (fresh vals)
        ull O0 = fresh0 ? enc_key(sc2.x, 2 * a0 + 1)
                        : ((E0 & ~0xFFull) | (ull)(127 - (2 * a0 + 1)));
        ull O1 = fresh1 ? enc_key(sc2.y, 2 * a1 + 1)
                        : ((E1 & ~0xFFull) | (ull)(127 - (2 * a1 + 1)));

        // desc bitonic sort of 64 odds, 2/lane (R8/R9-validated network)
        #pragma unroll
        for (int kk = 2; kk <= 64; kk <<= 1) {
            #pragma unroll
            for (int j2 = kk >> 1; j2 > 0; j2 >>= 1) {
                bool grp0 = ((a0 & kk) == 0);
                if (j2 == 1) {
                    ull mxv = umax64(O0, O1), mnv = umin64(O0, O1);
                    O0 = grp0 ? mxv : mnv;
                    O1 = grp0 ? mnv : mxv;
                } else {
                    int jh = j2 >> 1;
                    ull b0 = __shfl_xor_sync(FULL, O0, jh);
                    ull b1 = __shfl_xor_sync(FULL, O1, jh);
                    bool mx = (((lane & jh) == 0) == grp0);
                    O0 = mx ? umax64(O0, b0) : umin64(O0, b0);
                    O1 = mx ? umax64(O1, b1) : umin64(O1, b1);
                }
            }
        }

        // combine: evens (sorted, reindexed to idx 2*slot) vs reversed odds
        ull rev0 = __shfl_sync(FULL, O1, 31 - lane);
        ull rev1 = __shfl_sync(FULL, O0, 31 - lane);
        E0 = (E0 & ~0xFFull) | (ull)(127 - 4 * lane);
        E1 = (E1 & ~0xFFull) | (ull)(127 - (4 * lane + 2));
        E0 = umax64(E0, rev0);              // top-64 multiset, bitonic
        E1 = umax64(E1, rev1);

        // 6-stage desc merge -> sorted (skipped at final level: epilogue is
        // set-order invariant — validated R6/R8/R9)
        if (it < 6) {
            #pragma unroll
            for (int j2 = 32; j2 > 1; j2 >>= 1) {
                int jh = j2 >> 1;
                ull b0 = __shfl_xor_sync(FULL, E0, jh);
                ull b1 = __shfl_xor_sync(FULL, E1, jh);
                bool mx = ((lane & jh) == 0);
                E0 = mx ? umax64(E0, b0) : umin64(E0, b0);
                E1 = mx ? umax64(E1, b1) : umin64(E1, b1);
            }
            ull mxv = umax64(E0, E1), mnv = umin64(E0, E1);
            E0 = mxv; E1 = mnv;
        }

        // decode next-level parents (zparw stable during this level)
        int e0 = 127 - (int)(E0 & 0xFF);
        int e1 = 127 - (int)(E1 & 0xFF);
        zp0 = 2 * zparw[e0 >> 1] + (e0 & 1);
        zp1 = 2 * zparw[e1 >> 1] + (e1 & 1);
    }

    // ------------- final attention over the 64 kept (warp-local) ------------
    {
        const float rf = tsrc * (1.0f / 2048.0f);
        int pos0 = min((int)rintf((float)zp0 * rf), SS - 1);
        int pos1 = min((int)rintf((float)zp1 * rf), SS - 1);
        bool v0 = ((float)pos0 < tsrc);
        bool v1 = ((float)pos1 < tsrc);
        float a0 = v0 ? dec_score(E0) * 0.125f : -1e9f;   // 1/sqrt(64)
        float a1 = v1 ? dec_score(E1) * 0.125f : -1e9f;

        float m = fmaxf(a0, a1);
        m = fmaxf(m, __shfl_xor_sync(FULL, m, 16));
        m = fmaxf(m, __shfl_xor_sync(FULL, m, 8));
        m = fmaxf(m, __shfl_xor_sync(FULL, m, 4));
        m = fmaxf(m, __shfl_xor_sync(FULL, m, 2));
        m = fmaxf(m, __shfl_xor_sync(FULL, m, 1));

        float e0 = v0 ? expf(a0 - m) : 0.0f;   // invalid: ref underflows to 0
        float e1 = v1 ? expf(a1 - m) : 0.0f;
        float s = e0 + e1;
        s += __shfl_xor_sync(FULL, s, 16);
        s += __shfl_xor_sync(FULL, s, 8);
        s += __shfl_xor_sync(FULL, s, 4);
        s += __shfl_xor_sync(FULL, s, 2);
        s += __shfl_xor_sync(FULL, s, 1);

        float p0 = (s > 0.0f) ? (e0 / s) : 0.0f;  // all-invalid -> 0 (ref)
        float p1 = (s > 0.0f) ? (e1 / s) : 0.0f;

        // pack (pos, p) per slot; one STS.128 per lane
        ull pk0 = ((ull)(unsigned)pos0 << 32) | __float_as_uint(p0);
        ull pk1 = ((ull)(unsigned)pos1 << 32) | __float_as_uint(p1);
        ((ulonglong2*)pkw)[lane] = make_ulonglong2(pk0, pk1);
        __syncwarp();

        // R10-validated gather: thread pair-h layout, uint4 pack reads
        const float* vb = v + (size_t)n * SS * HH;
        float acc0 = 0.0f, acc1 = 0.0f;
        #pragma unroll 4
        for (int kk = 0; kk < 32; ++kk) {
            uint4 u = ((const uint4*)pkw)[kk];     // 2 packed entries
            float pa  = __uint_as_float(u.x);
            int   psa = (int)u.y;
            float pb  = __uint_as_float(u.z);
            int   psb = (int)u.w;
            float2 va = *(const float2*)(vb + (size_t)psa * HH + 2 * lane);
            acc0 = fmaf(pa, va.x, acc0);
            acc1 = fmaf(pa, va.y, acc1);
            float2 vbv = *(const float2*)(vb + (size_t)psb * HH + 2 * lane);
            acc0 = fmaf(pb, vbv.x, acc0);
            acc1 = fmaf(pb, vbv.y, acc1);
        }
        ((float2*)(out + ((size_t)(n * TT + t)) * HH))[lane] =
            make_float2(acc0, acc1);
    }
    #undef SCORE4
}

extern "C" void kernel_launch(void* const* d_in, const int* in_sizes, int n_in,
                              void* d_out, int out_size)
{
    const float* q = (const float*)d_in[0];
    const float* k = (const float*)d_in[1];
    const float* v = (const float*)d_in[2];
    float* out = (float*)d_out;
    (void)in_sizes; (void)n_in; (void)out_size;

    tree_attn_kernel<<<(NBATCH * TT) / 2, 64>>>(q, k, v, out);
}

// round 17
// speedup vs baseline: 1.1475x; 1.0056x over previous
#include <cuda_runtime.h>
#include <stdint.h>

#define NBATCH 16
#define TT     2048
#define SS     2048
#define HH     64

typedef unsigned long long ull;

__device__ __forceinline__ ull umax64(ull a, ull b) { return a > b ? a : b; }
__device__ __forceinline__ ull umin64(ull a, ull b) { return a < b ? a : b; }

// key = (sortable_score << 8) | (127 - expanded_idx); numeric DESC order ==
// desc by score, ties by ascending index (replicates lax.top_k exactly,
// given equal pos -> bit-equal score).
__device__ __forceinline__ ull enc_key(float s, int idx) {
    unsigned u  = __float_as_uint(s);
    unsigned su = (u & 0x80000000u) ? ~u : (u | 0x80000000u);
    return ((ull)su << 8) | (ull)(127 - idx);
}
__device__ __forceinline__ float dec_score(ull k) {
    unsigned su = (unsigned)(k >> 8);
    unsigned u  = (su & 0x80000000u) ? (su & 0x7FFFFFFFu) : ~su;
    return __uint_as_float(u);
}

__global__ __launch_bounds__(64, 32)
void tree_attn_kernel(const float* __restrict__ q,
                      const float* __restrict__ kmat,
                      const float* __restrict__ v,
                      float* __restrict__ out)
{
    // per-warp private scratch (one row per warp; NO block barriers anywhere)
    __shared__ float              sc_s[2][68];   // fresh scores by child slot
    __shared__ int                zpar_s[2][64]; // parent z values
    __shared__ __align__(8) int2  fl_s[2][68];   // compacted fresh list (+pads)
    __shared__ __align__(16) ull  pk_s[2][64];   // epilogue (pos,p) packs

    const int wid  = threadIdx.x >> 5;
    const int lane = threadIdx.x & 31;
    const int row  = blockIdx.x * 2 + wid;
    const int n    = row >> 11;
    const int t    = row & (TT - 1);
    const float tsrc = (float)(t + 1);
    const int l8   = lane & 7;           // lane within 8-lane scoring group
    const int grp  = lane >> 3;          // scoring group 0..3
    const unsigned FULL = 0xffffffffu;
    const unsigned LT   = (1u << lane) - 1u;

    float* scw   = sc_s[wid];
    int*   zparw = zpar_s[wid];
    int2*  flw   = fl_s[wid];
    ull*   pkw   = pk_s[wid];

    const float* kbase = kmat + (size_t)n * SS * HH;
    const float4* qrow = (const float4*)(q + ((size_t)(n * TT + t)) * HH);
    const float4 qA = qrow[l8];       // chunk l8      (row line 0)
    const float4 qB = qrow[l8 + 8];   // chunk l8 + 8  (row line 1)

    // R14-validated line-clean rebuild of the pinned R3 reduction DAG:
    // kA touches only line 0 of the key row, kB only line 1. Two parallel
    // 8-leaf trees; part = d0 + d8. Bit-equal to R3 by IEEE commutativity.
    // 4 candidates per warp pass. DO NOT re-associate.
    #define SCORE4(PP, SLOT)                                                  \
        {                                                                     \
            const float4* krow = (const float4*)(kbase + (size_t)(PP) * HH);  \
            float4 kA = krow[l8];                                             \
            float4 kB = krow[l8 + 8];                                         \
            float u = qA.x * kA.x + qA.y * kA.y + qA.z * kA.z + qA.w * kA.w;  \
            float w = qB.x * kB.x + qB.y * kB.y + qB.z * kB.z + qB.w * kB.w;  \
            u += __shfl_xor_sync(FULL, u, 1);                                 \
            w += __shfl_xor_sync(FULL, w, 1);                                 \
            u += __shfl_xor_sync(FULL, u, 2);                                 \
            w += __shfl_xor_sync(FULL, w, 2);                                 \
            u += __shfl_xor_sync(FULL, u, 4);                                 \
            w += __shfl_xor_sync(FULL, w, 4);                                 \
            float part = u + w;                                               \
            if (l8 == 0) scw[SLOT] = part;                                    \
        }

    // ------------- it0: 32 fresh candidates (z = c), w2 = 32 ----------------
    ull key;   // after it0: lane = rank, sorted desc
    {
        const float r = tsrc * (1.0f / 32.0f);
        #pragma unroll
        for (int j = 0; j < 8; ++j) {
            int c  = 4 * j + grp;
            int pp = min((int)rintf((float)c * r), SS - 1);
            SCORE4(pp, c)
        }
        __syncwarp();
        key = enc_key(scw[lane], lane);      // idx == z at level 0
        #pragma unroll
        for (int kk = 2; kk <= 32; kk <<= 1)
            #pragma unroll
            for (int j2 = kk >> 1; j2 > 0; j2 >>= 1) {
                ull p = __shfl_xor_sync(FULL, key, j2);
                bool mx = (((lane & j2) == 0) == ((lane & kk) == 0));
                key = mx ? umax64(key, p) : umin64(key, p);
            }
    }

    ull E0, E1;      // kept keys at slots 2t/2t+1 (2-packed state)
    int zp0, zp1;    // parent z at slots 2t/2t+1

    // ------------- it1 special: 32 parents -> keep all 64, w2 = 64 ----------
    {
        const float r = tsrc * (1.0f / 64.0f);
        int zpar1 = 127 - (int)(key & 0xFF);  // parent z, rank = lane
        int pE = min((int)rintf((float)(2 * zpar1) * r),     SS - 1);
        int pO = min((int)rintf((float)(2 * zpar1 + 1) * r), SS - 1);
        bool fresh = (pO != pE);
        zparw[lane] = zpar1;

        unsigned m = __ballot_sync(FULL, fresh);
        int nF = __popc(m);
        if (fresh) flw[__popc(m & LT)] = make_int2(pO, lane);
        if (lane < 3) flw[nF + lane] = make_int2(0, 64 + lane);  // pads
        __syncwarp();
        for (int j = 0; j < nF; j += 4) {
            int2 ent = flw[j + grp];
            SCORE4(ent.x, ent.y)
        }
        __syncwarp();

        // odd key per lane (rank = lane): fresh score or inherited key bits
        ull okey = fresh ? enc_key(scw[lane], 2 * lane + 1)
                         : ((key & ~0xFFull) | (ull)(127 - (2 * lane + 1)));
        // 15-stage desc bitonic sort of the 32 odds (1 key/lane)
        #pragma unroll
        for (int kk = 2; kk <= 32; kk <<= 1)
            #pragma unroll
            for (int j2 = kk >> 1; j2 > 0; j2 >>= 1) {
                ull p = __shfl_xor_sync(FULL, okey, j2);
                bool mx = (((lane & j2) == 0) == ((lane & kk) == 0));
                okey = mx ? umax64(okey, p) : umin64(okey, p);
            }

        // distribute into 2-packed slot space: [32 real desc | 32 zeros]
        ull O0 = __shfl_sync(FULL, okey, (2 * lane) & 31);
        ull O1 = __shfl_sync(FULL, okey, (2 * lane + 1) & 31);
        ull k0e = __shfl_sync(FULL, key, (2 * lane) & 31);
        ull k1e = __shfl_sync(FULL, key, (2 * lane + 1) & 31);
        bool lo = lane < 16;
        if (!lo) { O0 = 0ull; O1 = 0ull; }
        // evens: parent rank 2t -> expanded idx 4t (pads zero)
        E0 = lo ? ((k0e & ~0xFFull) | (ull)(127 - 4 * lane)) : 0ull;
        E1 = lo ? ((k1e & ~0xFFull) | (ull)(127 - (4 * lane + 2))) : 0ull;

        // combine + full 6-stage desc merge -> all 64 kept, sorted
        ull rev0 = __shfl_sync(FULL, O1, 31 - lane);
        ull rev1 = __shfl_sync(FULL, O0, 31 - lane);
        E0 = umax64(E0, rev0);
        E1 = umax64(E1, rev1);
        #pragma unroll
        for (int j2 = 32; j2 > 1; j2 >>= 1) {
            int jh = j2 >> 1;
            ull b0 = __shfl_xor_sync(FULL, E0, jh);
            ull b1 = __shfl_xor_sync(FULL, E1, jh);
            bool mx = ((lane & jh) == 0);
            E0 = mx ? umax64(E0, b0) : umin64(E0, b0);
            E1 = mx ? umax64(E1, b1) : umin64(E1, b1);
        }
        ull mxv = umax64(E0, E1), mnv = umin64(E0, E1);
        E0 = mxv; E1 = mnv;

        int e0 = 127 - (int)(E0 & 0xFF);
        int e1 = 127 - (int)(E1 & 0xFF);
        zp0 = 2 * zparw[e0 >> 1] + (e0 & 1);
        zp1 = 2 * zparw[e1 >> 1] + (e1 & 1);
    }

    // ------------- levels it = 2..6: 64 parents -> top-64 of 128 ------------
    #pragma unroll 1
    for (int it = 2; it < 7; ++it) {
        const float r  = tsrc / (float)(32 << it);
        const int   a0 = 2 * lane, a1 = 2 * lane + 1;   // parent ranks

        // per-candidate collision skip: odd child landing on the even
        // sibling's token has a score bit-equal to the parent's -> inherit
        // the key bits directly in-register (idx byte swapped).
        int pE0 = min((int)rintf((float)(2 * zp0) * r),     SS - 1);
        int pO0 = min((int)rintf((float)(2 * zp0 + 1) * r), SS - 1);
        int pE1 = min((int)rintf((float)(2 * zp1) * r),     SS - 1);
        int pO1 = min((int)rintf((float)(2 * zp1 + 1) * r), SS - 1);
        bool fresh0 = (pO0 != pE0);
        bool fresh1 = (pO1 != pE1);

        *(int2*)(zparw + a0) = make_int2(zp0, zp1);

        // compact fresh candidates into a dense worklist (pos, slot)
        unsigned m0 = __ballot_sync(FULL, fresh0);
        unsigned m1 = __ballot_sync(FULL, fresh1);
        int c0 = __popc(m0);
        int nF = c0 + __popc(m1);
        if (fresh0) flw[__popc(m0 & LT)]      = make_int2(pO0, a0);
        if (fresh1) flw[c0 + __popc(m1 & LT)] = make_int2(pO1, a1);
        if (lane < 3) flw[nF + lane] = make_int2(0, 64 + lane);  // pads
        __syncwarp();

        // uniform scoring passes over the compacted list (4 per pass)
        for (int j = 0; j < nF; j += 4) {
            int2 ent = flw[j + grp];
            SCORE4(ent.x, ent.y)
        }
        __syncwarp();

        // odd keys 2/lane (expanded idx = 2*rank+1); inherited odds reuse the
        // parent's score bits in-register
        float2 sc2 = *(const float2*)(scw + a0);     // one LDS.64 (fresh vals)
        ull O0 = fresh0 ? enc_key(sc2.x, 2 * a0 + 1)
                        : ((E0 & ~0xFFull) | (ull)(127 - (2 * a0 + 1)));
        ull O1 = fresh1 ? enc_key(sc2.y, 2 * a1 + 1)
                        : ((E1 & ~0xFFull) | (ull)(127 - (2 * a1 + 1)));

        // desc bitonic sort of 64 odds, 2/lane (R8/R9-validated network)
        #pragma unroll
        for (int kk = 2; kk <= 64; kk <<= 1) {
            #pragma unroll
            for (int j2 = kk >> 1; j2 > 0; j2 >>= 1) {
                bool grp0 = ((a0 & kk) == 0);
                if (j2 == 1) {
                    ull mxv = umax64(O0, O1), mnv = umin64(O0, O1);
                    O0 = grp0 ? mxv : mnv;
                    O1 = grp0 ? mnv : mxv;
                } else {
                    int jh = j2 >> 1;
                    ull b0 = __shfl_xor_sync(FULL, O0, jh);
                    ull b1 = __shfl_xor_sync(FULL, O1, jh);
                    bool mx = (((lane & jh) == 0) == grp0);
                    O0 = mx ? umax64(O0, b0) : umin64(O0, b0);
                    O1 = mx ? umax64(O1, b1) : umin64(O1, b1);
                }
            }
        }

        // combine: evens (sorted, reindexed to idx 2*slot) vs reversed odds
        ull rev0 = __shfl_sync(FULL, O1, 31 - lane);
        ull rev1 = __shfl_sync(FULL, O0, 31 - lane);
        E0 = (E0 & ~0xFFull) | (ull)(127 - 4 * lane);
        E1 = (E1 & ~0xFFull) | (ull)(127 - (4 * lane + 2));
        E0 = umax64(E0, rev0);              // top-64 multiset, bitonic
        E1 = umax64(E1, rev1);

        // 6-stage desc merge -> sorted (skipped at final level: epilogue is
        // set-order invariant — validated R6/R8/R9)
        if (it < 6) {
            #pragma unroll
            for (int j2 = 32; j2 > 1; j2 >>= 1) {
                int jh = j2 >> 1;
                ull b0 = __shfl_xor_sync(FULL, E0, jh);
                ull b1 = __shfl_xor_sync(FULL, E1, jh);
                bool mx = ((lane & jh) == 0);
                E0 = mx ? umax64(E0, b0) : umin64(E0, b0);
                E1 = mx ? umax64(E1, b1) : umin64(E1, b1);
            }
            ull mxv = umax64(E0, E1), mnv = umin64(E0, E1);
            E0 = mxv; E1 = mnv;
        }

        // decode next-level parents (zparw stable during this level)
        int e0 = 127 - (int)(E0 & 0xFF);
        int e1 = 127 - (int)(E1 & 0xFF);
        zp0 = 2 * zparw[e0 >> 1] + (e0 & 1);
        zp1 = 2 * zparw[e1 >> 1] + (e1 & 1);
    }

    // ------------- final attention over the 64 kept (warp-local) ------------
    {
        const float rf = tsrc * (1.0f / 2048.0f);
        int pos0 = min((int)rintf((float)zp0 * rf), SS - 1);
        int pos1 = min((int)rintf((float)zp1 * rf), SS - 1);
        bool v0 = ((float)pos0 < tsrc);
        bool v1 = ((float)pos1 < tsrc);
        float a0 = v0 ? dec_score(E0) * 0.125f : -1e9f;   // 1/sqrt(64)
        float a1 = v1 ? dec_score(E1) * 0.125f : -1e9f;

        float m = fmaxf(a0, a1);
        m = fmaxf(m, __shfl_xor_sync(FULL, m, 16));
        m = fmaxf(m, __shfl_xor_sync(FULL, m, 8));
        m = fmaxf(m, __shfl_xor_sync(FULL, m, 4));
        m = fmaxf(m, __shfl_xor_sync(FULL, m, 2));
        m = fmaxf(m, __shfl_xor_sync(FULL, m, 1));

        float e0 = v0 ? expf(a0 - m) : 0.0f;   // invalid: ref underflows to 0
        float e1 = v1 ? expf(a1 - m) : 0.0f;
        float s = e0 + e1;
        s += __shfl_xor_sync(FULL, s, 16);
        s += __shfl_xor_sync(FULL, s, 8);
        s += __shfl_xor_sync(FULL, s, 4);
        s += __shfl_xor_sync(FULL, s, 2);
        s += __shfl_xor_sync(FULL, s, 1);

        float p0 = (s > 0.0f) ? (e0 / s) : 0.0f;  // all-invalid -> 0 (ref)
        float p1 = (s > 0.0f) ? (e1 / s) : 0.0f;

        // pack (pos, p) per slot; one STS.128 per lane
        ull pk0 = ((ull)(unsigned)pos0 << 32) | __float_as_uint(p0);
        ull pk1 = ((ull)(unsigned)pos1 << 32) | __float_as_uint(p1);
        ((ulonglong2*)pkw)[lane] = make_ulonglong2(pk0, pk1);
        __syncwarp();

        // R10-validated gather: thread pair-h layout, uint4 pack reads
        const float* vb = v + (size_t)n * SS * HH;
        float acc0 = 0.0f, acc1 = 0.0f;
        #pragma unroll 4
        for (int kk = 0; kk < 32; ++kk) {
            uint4 u = ((const uint4*)pkw)[kk];     // 2 packed entries
            float pa  = __uint_as_float(u.x);
            int   psa = (int)u.y;
            float pb  = __uint_as_float(u.z);
            int   psb = (int)u.w;
            float2 va = *(const float2*)(vb + (size_t)psa * HH + 2 * lane);
            acc0 = fmaf(pa, va.x, acc0);
            acc1 = fmaf(pa, va.y, acc1);
            float2 vbv = *(const float2*)(vb + (size_t)psb * HH + 2 * lane);
            acc0 = fmaf(pb, vbv.x, acc0);
            acc1 = fmaf(pb, vbv.y, acc1);
        }
        ((float2*)(out + ((size_t)(n * TT + t)) * HH))[lane] =
            make_float2(acc0, acc1);
    }
    #undef SCORE4
}

extern "C" void kernel_launch(void* const* d_in, const int* in_sizes, int n_in,
                              void* d_out, int out_size)
{
    const float* q = (const float*)d_in[0];
    const float* k = (const float*)d_in[1];
    const float* v = (const float*)d_in[2];
    float* out = (float*)d_out;
    (void)in_sizes; (void)n_in; (void)out_size;

    tree_attn_kernel<<<(NBATCH * TT) / 2, 64>>>(q, k, v, out);
}